// round 10
// baseline (speedup 1.0000x reference)
#include <cuda_runtime.h>
#include <cstdint>
#include <math.h>

// ---------------- problem constants ----------------
#define BB 2
#define HH 240
#define WW 1216
#define CHN 27
#define OC 81
#define HWSZ (HH*WW)
#define NPIX (BB*HWSZ)

#define GX 19            // 1216/64
#define GY 60            // 240/4
#define UCOL 128         // padded column stride in U (per k,c row)
#define UKB (27*UCOL*4)  // 13824 bytes per U_k buffer

// ---------------- device scratch ----------------
__device__ float g_conv[(size_t)OC * NPIX];              // conv output planes [oc][b][y][x]
__device__ __align__(16) float g_U[16 * 27 * UCOL];      // Winograd weights, warp-permuted

// ---------------- smem layout (bytes) ----------------
#define SM_BIAS 0                          // 96 floats -> 384
#define SM_PATCH 384                       // 27*6*68*4 = 44064
#define SM_V (384 + 44064)                 // 44448; 16*27*64*4 = 110592
#define SM_U (SM_V + 110592)               // 155040 (16B aligned); 2*13824 = 27648
#define SM_TOTAL (SM_U + 2*UKB)            // 182688

// ---------------- helpers ----------------
#define CP16(dst, src) asm volatile("cp.async.ca.shared.global [%0], [%1], 16;" :: "r"(dst), "l"(src))
#define CP_COMMIT() asm volatile("cp.async.commit_group;")
#define CP_WAIT1() asm volatile("cp.async.wait_group 1;")
#define CP_WAIT0() asm volatile("cp.async.wait_group 0;")

__device__ __forceinline__ uint32_t smem_u32(const void* p) {
    uint32_t a;
    asm("{ .reg .u64 t; cvta.to.shared.u64 t, %1; cvt.u32.u64 %0, t; }" : "=r"(a) : "l"(p));
    return a;
}

// ---------------- prep: U = G g G^T, warp-permuted [k][c][128] ----------------
// warp 0 -> ocs 0..5 at cols 0..5; warp w>=1 -> ocs 6+5(w-1)..6+5w-1 at cols 8w..8w+4
__global__ void prep_kernel(const float* __restrict__ conv_w) {
    int idx = blockIdx.x * 256 + threadIdx.x;
    if (idx >= 27 * UCOL) return;
    int c = idx / UCOL;
    int col = idx % UCOL;
    int w = col >> 3, j = col & 7;
    int oc = (w == 0) ? j : 6 + 5 * (w - 1) + j;
    bool valid = (w == 0) ? (j < 6) : (j < 5);
    if (valid && oc >= OC) valid = false;

    float U[4][4];
    if (valid) {
        float g[3][3];
        #pragma unroll
        for (int ky = 0; ky < 3; ky++)
            #pragma unroll
            for (int kx = 0; kx < 3; kx++)
                g[ky][kx] = conv_w[((oc * CHN + c) * 3 + ky) * 3 + kx];
        float T[4][3];
        #pragma unroll
        for (int kx = 0; kx < 3; kx++) {
            T[0][kx] = g[0][kx];
            T[1][kx] = 0.5f * (g[0][kx] + g[1][kx] + g[2][kx]);
            T[2][kx] = 0.5f * (g[0][kx] - g[1][kx] + g[2][kx]);
            T[3][kx] = g[2][kx];
        }
        #pragma unroll
        for (int r = 0; r < 4; r++) {
            U[r][0] = T[r][0];
            U[r][1] = 0.5f * (T[r][0] + T[r][1] + T[r][2]);
            U[r][2] = 0.5f * (T[r][0] - T[r][1] + T[r][2]);
            U[r][3] = T[r][2];
        }
    } else {
        #pragma unroll
        for (int r = 0; r < 4; r++)
            #pragma unroll
            for (int s = 0; s < 4; s++) U[r][s] = 0.f;
    }
    #pragma unroll
    for (int r = 0; r < 4; r++)
        #pragma unroll
        for (int s = 0; s < 4; s++)
            g_U[((r * 4 + s) * 27 + c) * UCOL + col] = U[r][s];
}

// ---------------- k-loop + epilogue, templated per warp class ----------------
// Y is declared HERE (never escapes through a pointer) -> guaranteed register residency.
template<int CNT>
__device__ __forceinline__ void conv_tail(uint8_t* smem, uint32_t sbase,
                                          int tid, int wid, int lane, int ocb,
                                          int bx, int by, int bz,
                                          const float* bias) {
    float2 Y[4][CNT];
    #pragma unroll
    for (int q = 0; q < 4; q++)
        #pragma unroll
        for (int j = 0; j < CNT; j++) Y[q][j] = make_float2(0.f, 0.f);

    #pragma unroll 1
    for (int k = 0; k < 16; k++) {
        if (k + 1 < 16) {
            const char* src = (const char*)g_U + (size_t)(k + 1) * UKB;
            uint32_t dst = sbase + SM_U + ((k + 1) & 1) * UKB;
            for (int j = tid; j < UKB / 16; j += 512)
                CP16(dst + j * 16, src + j * 16);
            CP_COMMIT();
            CP_WAIT1();
        } else {
            CP_WAIT0();
        }
        __syncthreads();

        const float* Uk = (const float*)(smem + SM_U + (k & 1) * UKB) + wid * 8;
        const float2* Vk = (const float2*)(smem + SM_V) + k * 27 * 32 + lane;

        float2 m[CNT];
        #pragma unroll
        for (int j = 0; j < CNT; j++) m[j] = make_float2(0.f, 0.f);
        #pragma unroll 3
        for (int c = 0; c < 27; c++) {
            float2 v = Vk[c * 32];
            float4 ua = *(const float4*)(Uk + c * UCOL);
            m[0].x = fmaf(ua.x, v.x, m[0].x); m[0].y = fmaf(ua.x, v.y, m[0].y);
            m[1].x = fmaf(ua.y, v.x, m[1].x); m[1].y = fmaf(ua.y, v.y, m[1].y);
            m[2].x = fmaf(ua.z, v.x, m[2].x); m[2].y = fmaf(ua.z, v.y, m[2].y);
            m[3].x = fmaf(ua.w, v.x, m[3].x); m[3].y = fmaf(ua.w, v.y, m[3].y);
            if (CNT == 6) {
                float2 ub = *(const float2*)(Uk + c * UCOL + 4);
                m[4].x = fmaf(ub.x, v.x, m[4].x); m[4].y = fmaf(ub.x, v.y, m[4].y);
                m[CNT-1].x = fmaf(ub.y, v.x, m[CNT-1].x); m[CNT-1].y = fmaf(ub.y, v.y, m[CNT-1].y);
            } else {
                float ub = Uk[c * UCOL + 4];
                m[4].x = fmaf(ub, v.x, m[4].x); m[4].y = fmaf(ub, v.y, m[4].y);
            }
        }

        int r = k >> 2, s = k & 3;
        float A0r = (r == 3) ? 0.f : 1.f;
        float A1r = (r == 0) ? 0.f : ((r == 1) ? 1.f : -1.f);
        float A0s = (s == 3) ? 0.f : 1.f;
        float A1s = (s == 0) ? 0.f : ((s == 1) ? 1.f : -1.f);
        float cc[4] = { A0r * A0s, A0r * A1s, A1r * A0s, A1r * A1s };
        #pragma unroll
        for (int q = 0; q < 4; q++) {
            if (cc[q] != 0.f) {
                #pragma unroll
                for (int j = 0; j < CNT; j++) {
                    Y[q][j].x = fmaf(cc[q], m[j].x, Y[q][j].x);
                    Y[q][j].y = fmaf(cc[q], m[j].y, Y[q][j].y);
                }
            }
        }
        __syncthreads();
    }

    // --- epilogue: bias + STG.128 ---
    const int xcol = 64 * bx + 4 * (lane & 15);
    const int row0 = 4 * by + 2 * (lane >> 4);
    const size_t base = (size_t)bz * HWSZ + xcol;
    #pragma unroll
    for (int j = 0; j < CNT; j++) {
        int oc = ocb + j;
        float bv = bias[oc];
        float* plane = g_conv + (size_t)oc * NPIX + base;
        float4 r0v = make_float4(Y[0][j].x + bv, Y[1][j].x + bv,
                                 Y[0][j].y + bv, Y[1][j].y + bv);
        float4 r1v = make_float4(Y[2][j].x + bv, Y[3][j].x + bv,
                                 Y[2][j].y + bv, Y[3][j].y + bv);
        *(float4*)(plane + (size_t)row0 * WW) = r0v;
        *(float4*)(plane + (size_t)(row0 + 1) * WW) = r1v;
    }
}

// ---------------- Winograd conv kernel: 512 threads, 16 warps, exact 81 oc ----------------
__global__ __launch_bounds__(512, 1)
void wino_kernel(const float* __restrict__ guide, const float* __restrict__ conv_b) {
    extern __shared__ uint8_t smem[];
    const uint32_t sbase = smem_u32(smem);
    const int tid = threadIdx.x;
    const int wid = tid >> 5;
    const int lane = tid & 31;
    const int bx = blockIdx.x, by = blockIdx.y, bz = blockIdx.z;

    // --- prefetch U_0 into buf 0 ---
    {
        const char* src = (const char*)g_U;
        uint32_t dst = sbase + SM_U;
        for (int j = tid; j < UKB / 16; j += 512)
            CP16(dst + j * 16, src + (size_t)j * 16);
        CP_COMMIT();
    }

    if (tid < 96) ((float*)(smem + SM_BIAS))[tid] = (tid < OC) ? conv_b[tid] : 0.f;

    // --- stage input patch: 27 ch x 6 rows x 66 cols (zero-padded), stride 68 ---
    {
        const int py0 = 4 * by - 1;
        const int px0 = 64 * bx - 1;
        float* patch = (float*)(smem + SM_PATCH);
        for (int i = tid; i < 27 * 6 * 66; i += 512) {
            int c = i / 396;
            int rr = (i / 66) % 6;
            int xx = i % 66;
            int gy = py0 + rr;
            int gx = px0 + xx;
            float v = 0.f;
            if ((unsigned)gy < HH && (unsigned)gx < WW)
                v = __ldg(&guide[((size_t)(bz * CHN + c) * HH + gy) * WW + gx]);
            patch[(c * 6 + rr) * 68 + xx] = v;
        }
    }
    __syncthreads();

    // --- input transform V = B^T d B; pair index t = tx + 32*tyl ---
    {
        const float* patch = (const float*)(smem + SM_PATCH);
        float* V = (float*)(smem + SM_V);
        for (int i = tid; i < 27 * 64; i += 512) {
            int c = i >> 6;
            int t = i & 63;
            int tx = t & 31;
            int tyl = t >> 5;
            const float* base = patch + (c * 6 + tyl * 2) * 68 + 2 * tx;
            float d[4][4];
            #pragma unroll
            for (int r = 0; r < 4; r++) {
                float2 p0 = *(const float2*)(base + r * 68);
                float2 p1 = *(const float2*)(base + r * 68 + 2);
                d[r][0] = p0.x; d[r][1] = p0.y; d[r][2] = p1.x; d[r][3] = p1.y;
            }
            float R[4][4];
            #pragma unroll
            for (int r = 0; r < 4; r++) {
                R[r][0] = d[r][0] - d[r][2];
                R[r][1] = d[r][1] + d[r][2];
                R[r][2] = d[r][2] - d[r][1];
                R[r][3] = d[r][1] - d[r][3];
            }
            #pragma unroll
            for (int s = 0; s < 4; s++) {
                V[((0 * 4 + s) * 27 + c) * 64 + t] = R[0][s] - R[2][s];
                V[((1 * 4 + s) * 27 + c) * 64 + t] = R[1][s] + R[2][s];
                V[((2 * 4 + s) * 27 + c) * 64 + t] = R[2][s] - R[1][s];
                V[((3 * 4 + s) * 27 + c) * 64 + t] = R[1][s] - R[3][s];
            }
        }
    }
    // V visibility covered by the first in-loop barrier.

    const float* bias = (const float*)(smem + SM_BIAS);
    if (wid == 0) conv_tail<6>(smem, sbase, tid, wid, lane, 0, bx, by, bz, bias);
    else          conv_tail<5>(smem, sbase, tid, wid, lane, 6 + 5 * (wid - 1), bx, by, bz, bias);
}

// ---------------- propagation: 2 pixels/thread, softmax + bilinear + blend ----------------
__device__ __constant__ float TAPX[9] = {-1.f, 0.f, 1.f, -1.f, 0.f, 1.f, -1.f, 0.f, 1.f};
__device__ __constant__ float TAPY[9] = {-1.f, -1.f, -1.f, 0.f, 0.f, 0.f, 1.f, 1.f, 1.f};

__global__ void prop_kernel(const float* __restrict__ prev,
                            const float* __restrict__ sp_dep,
                            const float* __restrict__ confid,
                            float* __restrict__ out_cur,
                            float* __restrict__ pred_out,
                            const float* __restrict__ feat_src,
                            float* __restrict__ feat_dst,
                            int iter) {
    int p2 = blockIdx.x * blockDim.x + threadIdx.x;   // pair index
    if (p2 >= NPIX / 2) return;
    int p = 2 * p2;

    // ---- front-loaded vector reads (float2 over consecutive pixels) ----
    float2 araw[9], ox[9], oy[9];
    #pragma unroll
    for (int t = 0; t < 9; t++)
        araw[t] = __ldg((const float2*)&g_conv[(size_t)(54 + iter * 9 + t) * NPIX + p]);
    #pragma unroll
    for (int t = 0; t < 9; t++) {
        ox[t] = __ldg((const float2*)&g_conv[(size_t)((iter * 9 + t) * 2) * NPIX + p]);
        oy[t] = __ldg((const float2*)&g_conv[(size_t)((iter * 9 + t) * 2 + 1) * NPIX + p]);
    }
    float2 sp2 = __ldg((const float2*)&sp_dep[p]);
    float2 cf2 = __ldg((const float2*)&confid[p]);

    float outv[2];
    #pragma unroll
    for (int h = 0; h < 2; h++) {
        int pp = p + h;
        int b = pp / HWSZ;
        int rem = pp % HWSZ;
        int y = rem / WW;
        int x = rem % WW;
        const float* img = prev + (size_t)b * HWSZ;

        float a0 = (h == 0) ? araw[0].x : araw[0].y;
        float mx = a0;
        float av[9];
        av[0] = a0;
        #pragma unroll
        for (int t = 1; t < 9; t++) {
            av[t] = (h == 0) ? araw[t].x : araw[t].y;
            mx = fmaxf(mx, av[t]);
        }
        float wv[9];
        float s = 0.f;
        #pragma unroll
        for (int t = 0; t < 9; t++) { wv[t] = __expf(av[t] - mx); s += wv[t]; }
        float inv = 1.f / s;

        float agg = 0.f;
        #pragma unroll
        for (int t = 0; t < 9; t++) {
            float oxv = (h == 0) ? ox[t].x : ox[t].y;
            float oyv = (h == 0) ? oy[t].x : oy[t].y;
            float px = oxv + TAPX[t] + (float)x;
            float py = oyv + TAPY[t] + (float)y;
            float x0f = floorf(px), y0f = floorf(py);
            int xi = (int)x0f, yi = (int)y0f;
            float wx = px - x0f, wy = py - y0f;

            float v00 = 0.f, v01 = 0.f, v10 = 0.f, v11 = 0.f;
            bool xa = (xi >= 0) & (xi < WW);
            bool xb2 = (xi + 1 >= 0) & (xi + 1 < WW);
            bool ya = (yi >= 0) & (yi < HH);
            bool yb = (yi + 1 >= 0) & (yi + 1 < HH);
            if (ya) {
                const float* r0 = img + (size_t)yi * WW;
                if (xa) v00 = __ldg(r0 + xi);
                if (xb2) v01 = __ldg(r0 + xi + 1);
            }
            if (yb) {
                const float* r1 = img + (size_t)(yi + 1) * WW;
                if (xa) v10 = __ldg(r1 + xi);
                if (xb2) v11 = __ldg(r1 + xi + 1);
            }
            float v = (1.f - wy) * ((1.f - wx) * v00 + wx * v01)
                    + wy * ((1.f - wx) * v10 + wx * v11);
            agg += wv[t] * v;
        }
        agg *= inv;

        float sp = (h == 0) ? sp2.x : sp2.y;
        float cfr = (h == 0) ? cf2.x : cf2.y;
        float cf = 1.f / (1.f + __expf(-cfr));
        float sg = (sp > 0.f) ? 1.f : ((sp < 0.f) ? -1.f : 0.f);
        cf *= sg;
        outv[h] = (1.f - cf) * agg + cf * sp;
    }

    float2 o2 = make_float2(outv[0], outv[1]);
    *(float2*)&out_cur[p] = o2;
    if (pred_out) *(float2*)&pred_out[p] = o2;
    if (feat_dst) *(float2*)&feat_dst[p] = __ldg((const float2*)&feat_src[p]);
}

// ---------------- launch ----------------
extern "C" void kernel_launch(void* const* d_in, const int* in_sizes, int n_in,
                              void* d_out, int out_size) {
    const float* input  = (const float*)d_in[0];
    const float* guide  = (const float*)d_in[1];
    const float* sp_dep = (const float*)d_in[2];
    const float* confid = (const float*)d_in[3];
    const float* conv_w = (const float*)d_in[4];
    const float* conv_b = (const float*)d_in[5];

    float* out = (float*)d_out;
    float* pred = out;
    float* feat = out + NPIX;
    float* inter = out + 2 * (size_t)NPIX;

    static bool attr_set = false;
    if (!attr_set) {
        cudaFuncSetAttribute(wino_kernel, cudaFuncAttributeMaxDynamicSharedMemorySize, SM_TOTAL);
        attr_set = true;
    }

    prep_kernel<<<(27 * UCOL + 255) / 256, 256>>>(conv_w);

    dim3 wgrid(GX, GY, BB);
    wino_kernel<<<wgrid, 512, SM_TOTAL>>>(guide, conv_b);

    int pb = (NPIX / 2 + 255) / 256;
    prop_kernel<<<pb, 256>>>(input, sp_dep, confid, inter, nullptr, input, feat, 0);
    prop_kernel<<<pb, 256>>>(inter, sp_dep, confid, inter + NPIX, nullptr, nullptr, nullptr, 1);
    prop_kernel<<<pb, 256>>>(inter + NPIX, sp_dep, confid, inter + 2 * (size_t)NPIX, pred, nullptr, nullptr, 2);
}

// round 11
// speedup vs baseline: 1.0399x; 1.0399x over previous
#include <cuda_runtime.h>
#include <cstdint>
#include <math.h>

// ---------------- problem constants ----------------
#define BB 2
#define HH 240
#define WW 1216
#define CHN 27
#define OC 81
#define HWSZ (HH*WW)
#define NPIX (BB*HWSZ)

#define GX 19            // 1216/64
#define GY 60            // 240/4
#define UCOL 128         // padded column stride in U (per k,c row)
#define UKB (27*UCOL*4)  // 13824 bytes per U_k buffer

// ---------------- device scratch ----------------
__device__ float g_conv[(size_t)OC * NPIX];              // conv output planes [oc][b][y][x]
__device__ __align__(16) float g_U[16 * 27 * UCOL];      // Winograd weights, warp-permuted

// ---------------- smem layout (bytes) ----------------
#define SM_BIAS 0                          // 96 floats -> 384
#define SM_PATCH 384                       // 27*6*68*4 = 44064
#define SM_V (384 + 44064)                 // 44448; 16*27*64*4 = 110592
#define SM_U (SM_V + 110592)               // 155040 (16B aligned); 2*13824 = 27648
#define SM_TOTAL (SM_U + 2*UKB)            // 182688

// ---------------- helpers ----------------
#define CP16(dst, src) asm volatile("cp.async.ca.shared.global [%0], [%1], 16;" :: "r"(dst), "l"(src))
#define CP_COMMIT() asm volatile("cp.async.commit_group;")
#define CP_WAIT1() asm volatile("cp.async.wait_group 1;")
#define CP_WAIT0() asm volatile("cp.async.wait_group 0;")

__device__ __forceinline__ uint32_t smem_u32(const void* p) {
    uint32_t a;
    asm("{ .reg .u64 t; cvta.to.shared.u64 t, %1; cvt.u32.u64 %0, t; }" : "=r"(a) : "l"(p));
    return a;
}

// ---------------- prep: U = G g G^T, warp-permuted [k][c][128] ----------------
// oc = 6*w + j  ->  column 8*w + j  (w = 0..15, j = 0..5)
__global__ void prep_kernel(const float* __restrict__ conv_w) {
    int idx = blockIdx.x * 256 + threadIdx.x;
    if (idx >= 27 * 96) return;
    int c = idx / 96;
    int oc = idx % 96;
    float U[4][4];
    if (oc < OC) {
        float g[3][3];
        #pragma unroll
        for (int ky = 0; ky < 3; ky++)
            #pragma unroll
            for (int kx = 0; kx < 3; kx++)
                g[ky][kx] = conv_w[((oc * CHN + c) * 3 + ky) * 3 + kx];
        float T[4][3];
        #pragma unroll
        for (int kx = 0; kx < 3; kx++) {
            T[0][kx] = g[0][kx];
            T[1][kx] = 0.5f * (g[0][kx] + g[1][kx] + g[2][kx]);
            T[2][kx] = 0.5f * (g[0][kx] - g[1][kx] + g[2][kx]);
            T[3][kx] = g[2][kx];
        }
        #pragma unroll
        for (int r = 0; r < 4; r++) {
            U[r][0] = T[r][0];
            U[r][1] = 0.5f * (T[r][0] + T[r][1] + T[r][2]);
            U[r][2] = 0.5f * (T[r][0] - T[r][1] + T[r][2]);
            U[r][3] = T[r][2];
        }
    } else {
        #pragma unroll
        for (int r = 0; r < 4; r++)
            #pragma unroll
            for (int s = 0; s < 4; s++) U[r][s] = 0.f;
    }
    int w = oc / 6, j = oc % 6;
    int col = 8 * w + j;
    #pragma unroll
    for (int r = 0; r < 4; r++)
        #pragma unroll
        for (int s = 0; s < 4; s++)
            g_U[((r * 4 + s) * 27 + c) * UCOL + col] = U[r][s];
    // zero the never-written pad columns 8w+6, 8w+7 once (idx mapping reuse)
    if (oc < 32) {   // 16 warps x 2 pad cols
        int w2 = oc >> 1, jp = 6 + (oc & 1);
        #pragma unroll
        for (int k = 0; k < 16; k++)
            g_U[(k * 27 + c) * UCOL + 8 * w2 + jp] = 0.f;
    }
}

// ---------------- Winograd conv kernel: 512 threads, 16 warps x 6 oc ----------------
__global__ __launch_bounds__(512, 1)
void wino_kernel(const float* __restrict__ guide, const float* __restrict__ conv_b) {
    extern __shared__ uint8_t smem[];
    const uint32_t sbase = smem_u32(smem);
    const int tid = threadIdx.x;
    const int wid = tid >> 5;
    const int lane = tid & 31;
    const int bx = blockIdx.x, by = blockIdx.y, bz = blockIdx.z;

    // --- prefetch U_0 ---
    {
        const char* src = (const char*)g_U;
        uint32_t dst = sbase + SM_U;
        for (int j = tid; j < UKB / 16; j += 512)
            CP16(dst + j * 16, src + (size_t)j * 16);
        CP_COMMIT();
    }

    if (tid < 96) ((float*)(smem + SM_BIAS))[tid] = (tid < OC) ? conv_b[tid] : 0.f;

    // --- stage input patch: 27 ch x 6 rows x 66 cols (zero-padded), stride 68 ---
    {
        const int py0 = 4 * by - 1;
        const int px0 = 64 * bx - 1;
        float* patch = (float*)(smem + SM_PATCH);
        for (int i = tid; i < 27 * 6 * 66; i += 512) {
            int c = i / 396;
            int rr = (i / 66) % 6;
            int xx = i % 66;
            int gy = py0 + rr;
            int gx = px0 + xx;
            float v = 0.f;
            if ((unsigned)gy < HH && (unsigned)gx < WW)
                v = __ldg(&guide[((size_t)(bz * CHN + c) * HH + gy) * WW + gx]);
            patch[(c * 6 + rr) * 68 + xx] = v;
        }
    }
    __syncthreads();

    // --- input transform V = B^T d B; pair index t = tx + 32*tyl ---
    {
        const float* patch = (const float*)(smem + SM_PATCH);
        float* V = (float*)(smem + SM_V);
        for (int i = tid; i < 27 * 64; i += 512) {
            int c = i >> 6;
            int t = i & 63;
            int tx = t & 31;
            int tyl = t >> 5;
            const float* base = patch + (c * 6 + tyl * 2) * 68 + 2 * tx;
            float d[4][4];
            #pragma unroll
            for (int r = 0; r < 4; r++) {
                float2 p0 = *(const float2*)(base + r * 68);
                float2 p1 = *(const float2*)(base + r * 68 + 2);
                d[r][0] = p0.x; d[r][1] = p0.y; d[r][2] = p1.x; d[r][3] = p1.y;
            }
            float R[4][4];
            #pragma unroll
            for (int r = 0; r < 4; r++) {
                R[r][0] = d[r][0] - d[r][2];
                R[r][1] = d[r][1] + d[r][2];
                R[r][2] = d[r][2] - d[r][1];
                R[r][3] = d[r][1] - d[r][3];
            }
            #pragma unroll
            for (int s = 0; s < 4; s++) {
                V[((0 * 4 + s) * 27 + c) * 64 + t] = R[0][s] - R[2][s];
                V[((1 * 4 + s) * 27 + c) * 64 + t] = R[1][s] + R[2][s];
                V[((2 * 4 + s) * 27 + c) * 64 + t] = R[2][s] - R[1][s];
                V[((3 * 4 + s) * 27 + c) * 64 + t] = R[1][s] - R[3][s];
            }
        }
    }
    __syncthreads();

    // --- 16 position-GEMMs with fused output transform ---
    float2 Y[4][6];
    #pragma unroll
    for (int q = 0; q < 4; q++)
        #pragma unroll
        for (int j = 0; j < 6; j++) Y[q][j] = make_float2(0.f, 0.f);

    #pragma unroll 1
    for (int k = 0; k < 16; k++) {
        if (k + 1 < 16) {
            const char* src = (const char*)g_U + (size_t)(k + 1) * UKB;
            uint32_t dst = sbase + SM_U + ((k + 1) & 1) * UKB;
            for (int j = tid; j < UKB / 16; j += 512)
                CP16(dst + j * 16, src + j * 16);
            CP_COMMIT();
            CP_WAIT1();
        } else {
            CP_WAIT0();
        }
        __syncthreads();

        const float* Uk = (const float*)(smem + SM_U + (k & 1) * UKB) + wid * 8;
        const float2* Vk = (const float2*)(smem + SM_V) + k * 27 * 32 + lane;

        float2 m[6];
        #pragma unroll
        for (int j = 0; j < 6; j++) m[j] = make_float2(0.f, 0.f);
        #pragma unroll
        for (int c = 0; c < 27; c++) {
            float2 v = Vk[c * 32];
            float4 ua = *(const float4*)(Uk + c * UCOL);
            float2 ub = *(const float2*)(Uk + c * UCOL + 4);
            m[0].x = fmaf(ua.x, v.x, m[0].x); m[0].y = fmaf(ua.x, v.y, m[0].y);
            m[1].x = fmaf(ua.y, v.x, m[1].x); m[1].y = fmaf(ua.y, v.y, m[1].y);
            m[2].x = fmaf(ua.z, v.x, m[2].x); m[2].y = fmaf(ua.z, v.y, m[2].y);
            m[3].x = fmaf(ua.w, v.x, m[3].x); m[3].y = fmaf(ua.w, v.y, m[3].y);
            m[4].x = fmaf(ub.x, v.x, m[4].x); m[4].y = fmaf(ub.x, v.y, m[4].y);
            m[5].x = fmaf(ub.y, v.x, m[5].x); m[5].y = fmaf(ub.y, v.y, m[5].y);
        }

        // output-transform accumulation: coef(p,q) = A_p[r]*A_q[s]
        int r = k >> 2, s = k & 3;
        float A0r = (r == 3) ? 0.f : 1.f;
        float A1r = (r == 0) ? 0.f : ((r == 1) ? 1.f : -1.f);
        float A0s = (s == 3) ? 0.f : 1.f;
        float A1s = (s == 0) ? 0.f : ((s == 1) ? 1.f : -1.f);
        float cc[4] = { A0r * A0s, A0r * A1s, A1r * A0s, A1r * A1s };
        #pragma unroll
        for (int q = 0; q < 4; q++) {
            if (cc[q] != 0.f) {
                #pragma unroll
                for (int j = 0; j < 6; j++) {
                    Y[q][j].x = fmaf(cc[q], m[j].x, Y[q][j].x);
                    Y[q][j].y = fmaf(cc[q], m[j].y, Y[q][j].y);
                }
            }
        }
        __syncthreads();
    }

    // --- epilogue: bias + STG.128 ---
    {
        const float* bias = (const float*)(smem + SM_BIAS);
        const int xcol = 64 * bx + 4 * (lane & 15);
        const int row0 = 4 * by + 2 * (lane >> 4);
        const size_t base = (size_t)bz * HWSZ + xcol;
        #pragma unroll
        for (int j = 0; j < 6; j++) {
            int oc = 6 * wid + j;
            if (oc >= OC) break;
            float bv = bias[oc];
            float* plane = g_conv + (size_t)oc * NPIX + base;
            float4 r0v = make_float4(Y[0][j].x + bv, Y[1][j].x + bv,
                                     Y[0][j].y + bv, Y[1][j].y + bv);
            float4 r1v = make_float4(Y[2][j].x + bv, Y[3][j].x + bv,
                                     Y[2][j].y + bv, Y[3][j].y + bv);
            *(float4*)(plane + (size_t)row0 * WW) = r0v;
            *(float4*)(plane + (size_t)(row0 + 1) * WW) = r1v;
        }
    }
}

// ---------------- propagation: softmax + bilinear-zeros + confidence blend ----------------
__device__ __constant__ float TAPX[9] = {-1.f, 0.f, 1.f, -1.f, 0.f, 1.f, -1.f, 0.f, 1.f};
__device__ __constant__ float TAPY[9] = {-1.f, -1.f, -1.f, 0.f, 0.f, 0.f, 1.f, 1.f, 1.f};

__global__ void prop_kernel(const float* __restrict__ prev,
                            const float* __restrict__ sp_dep,
                            const float* __restrict__ confid,
                            float* __restrict__ out_cur,
                            float* __restrict__ pred_out,
                            const float* __restrict__ feat_src,
                            float* __restrict__ feat_dst,
                            int iter) {
    int p = blockIdx.x * blockDim.x + threadIdx.x;
    if (p >= NPIX) return;
    int b = p / HWSZ;
    int rem = p % HWSZ;
    int y = rem / WW;
    int x = rem % WW;
    const float* img = prev + (size_t)b * HWSZ;

    // ---- front-load all independent global reads (max MLP) ----
    float araw[9], ox[9], oy[9];
    #pragma unroll
    for (int t = 0; t < 9; t++)
        araw[t] = __ldg(&g_conv[(size_t)(54 + iter * 9 + t) * NPIX + p]);
    #pragma unroll
    for (int t = 0; t < 9; t++) {
        ox[t] = __ldg(&g_conv[(size_t)((iter * 9 + t) * 2) * NPIX + p]);
        oy[t] = __ldg(&g_conv[(size_t)((iter * 9 + t) * 2 + 1) * NPIX + p]);
    }
    float sp = __ldg(&sp_dep[p]);
    float cfr = __ldg(&confid[p]);

    // softmax weights
    float mx = araw[0];
    #pragma unroll
    for (int t = 1; t < 9; t++) mx = fmaxf(mx, araw[t]);
    float wv[9];
    float s = 0.f;
    #pragma unroll
    for (int t = 0; t < 9; t++) { wv[t] = __expf(araw[t] - mx); s += wv[t]; }
    float inv = 1.f / s;

    float agg = 0.f;
    #pragma unroll
    for (int t = 0; t < 9; t++) {
        float px = ox[t] + TAPX[t] + (float)x;
        float py = oy[t] + TAPY[t] + (float)y;
        float x0f = floorf(px), y0f = floorf(py);
        int xi = (int)x0f, yi = (int)y0f;
        float wx = px - x0f, wy = py - y0f;

        float v00 = 0.f, v01 = 0.f, v10 = 0.f, v11 = 0.f;
        bool xa = (xi >= 0) & (xi < WW);
        bool xb2 = (xi + 1 >= 0) & (xi + 1 < WW);
        bool ya = (yi >= 0) & (yi < HH);
        bool yb = (yi + 1 >= 0) & (yi + 1 < HH);
        if (ya) {
            const float* r0 = img + (size_t)yi * WW;
            if (xa) v00 = __ldg(r0 + xi);
            if (xb2) v01 = __ldg(r0 + xi + 1);
        }
        if (yb) {
            const float* r1 = img + (size_t)(yi + 1) * WW;
            if (xa) v10 = __ldg(r1 + xi);
            if (xb2) v11 = __ldg(r1 + xi + 1);
        }
        float v = (1.f - wy) * ((1.f - wx) * v00 + wx * v01)
                + wy * ((1.f - wx) * v10 + wx * v11);
        agg += wv[t] * v;
    }
    agg *= inv;

    float cf = 1.f / (1.f + __expf(-cfr));
    float sg = (sp > 0.f) ? 1.f : ((sp < 0.f) ? -1.f : 0.f);
    cf *= sg;
    float o = (1.f - cf) * agg + cf * sp;

    out_cur[p] = o;
    if (pred_out) pred_out[p] = o;
    if (feat_dst) feat_dst[p] = feat_src[p];
}

// ---------------- launch ----------------
extern "C" void kernel_launch(void* const* d_in, const int* in_sizes, int n_in,
                              void* d_out, int out_size) {
    const float* input  = (const float*)d_in[0];
    const float* guide  = (const float*)d_in[1];
    const float* sp_dep = (const float*)d_in[2];
    const float* confid = (const float*)d_in[3];
    const float* conv_w = (const float*)d_in[4];
    const float* conv_b = (const float*)d_in[5];

    float* out = (float*)d_out;
    float* pred = out;
    float* feat = out + NPIX;
    float* inter = out + 2 * (size_t)NPIX;

    static bool attr_set = false;
    if (!attr_set) {
        cudaFuncSetAttribute(wino_kernel, cudaFuncAttributeMaxDynamicSharedMemorySize, SM_TOTAL);
        attr_set = true;
    }

    prep_kernel<<<(27 * 96 + 255) / 256, 256>>>(conv_w);

    dim3 wgrid(GX, GY, BB);
    wino_kernel<<<wgrid, 512, SM_TOTAL>>>(guide, conv_b);

    int pb = (NPIX + 255) / 256;
    prop_kernel<<<pb, 256>>>(input, sp_dep, confid, inter, nullptr, input, feat, 0);
    prop_kernel<<<pb, 256>>>(inter, sp_dep, confid, inter + NPIX, nullptr, nullptr, nullptr, 1);
    prop_kernel<<<pb, 256>>>(inter + NPIX, sp_dep, confid, inter + 2 * (size_t)NPIX, pred, nullptr, nullptr, 2);
}

// round 12
// speedup vs baseline: 1.5657x; 1.5056x over previous
#include <cuda_runtime.h>
#include <cstdint>
#include <math.h>

// ---------------- problem constants ----------------
#define BB 2
#define HH 240
#define WW 1216
#define CHN 27
#define OC 81
#define HWSZ (HH*WW)
#define NPIX (BB*HWSZ)

#define GX 19            // 1216/64
#define GY 60            // 240/4
#define UCOL 128         // padded column stride in U (per k,c row)
#define UKB (27*UCOL*4)  // 13824 bytes per U_k buffer

// ---------------- device scratch ----------------
__device__ float g_conv[(size_t)OC * NPIX];              // conv output planes [oc][b][y][x]
__device__ __align__(16) float g_U[16 * 27 * UCOL];      // Winograd weights, warp-permuted

// ---------------- smem layout (bytes) ----------------
#define SM_BIAS 0                          // 96 floats -> 384
#define SM_PATCH 384                       // 27*6*68*4 = 44064
#define SM_V (384 + 44064)                 // 44448; 16*27*64*4 = 110592
#define SM_U (SM_V + 110592)               // 155040 (16B aligned); 3*13824 = 41472
#define SM_TOTAL (SM_U + 3*UKB)            // 196512

// ---------------- helpers ----------------
#define CP16(dst, src) asm volatile("cp.async.ca.shared.global [%0], [%1], 16;" :: "r"(dst), "l"(src))
#define CP_COMMIT() asm volatile("cp.async.commit_group;")
#define CP_WAIT1() asm volatile("cp.async.wait_group 1;")
#define CP_WAIT0() asm volatile("cp.async.wait_group 0;")

__device__ __forceinline__ uint32_t smem_u32(const void* p) {
    uint32_t a;
    asm("{ .reg .u64 t; cvta.to.shared.u64 t, %1; cvt.u32.u64 %0, t; }" : "=r"(a) : "l"(p));
    return a;
}

// ---------------- prep: U = G g G^T, warp-permuted [k][c][128] ----------------
// oc = 6*w + j  ->  column 8*w + j  (w = 0..15, j = 0..5)
__global__ void prep_kernel(const float* __restrict__ conv_w) {
    int idx = blockIdx.x * 256 + threadIdx.x;
    if (idx >= 27 * 96) return;
    int c = idx / 96;
    int oc = idx % 96;
    float U[4][4];
    if (oc < OC) {
        float g[3][3];
        #pragma unroll
        for (int ky = 0; ky < 3; ky++)
            #pragma unroll
            for (int kx = 0; kx < 3; kx++)
                g[ky][kx] = conv_w[((oc * CHN + c) * 3 + ky) * 3 + kx];
        float T[4][3];
        #pragma unroll
        for (int kx = 0; kx < 3; kx++) {
            T[0][kx] = g[0][kx];
            T[1][kx] = 0.5f * (g[0][kx] + g[1][kx] + g[2][kx]);
            T[2][kx] = 0.5f * (g[0][kx] - g[1][kx] + g[2][kx]);
            T[3][kx] = g[2][kx];
        }
        #pragma unroll
        for (int r = 0; r < 4; r++) {
            U[r][0] = T[r][0];
            U[r][1] = 0.5f * (T[r][0] + T[r][1] + T[r][2]);
            U[r][2] = 0.5f * (T[r][0] - T[r][1] + T[r][2]);
            U[r][3] = T[r][2];
        }
    } else {
        #pragma unroll
        for (int r = 0; r < 4; r++)
            #pragma unroll
            for (int s = 0; s < 4; s++) U[r][s] = 0.f;
    }
    int w = oc / 6, j = oc % 6;
    int col = 8 * w + j;
    #pragma unroll
    for (int r = 0; r < 4; r++)
        #pragma unroll
        for (int s = 0; s < 4; s++)
            g_U[((r * 4 + s) * 27 + c) * UCOL + col] = U[r][s];
    // zero the never-written pad columns 8w+6, 8w+7 once (idx mapping reuse)
    if (oc < 32) {   // 16 warps x 2 pad cols
        int w2 = oc >> 1, jp = 6 + (oc & 1);
        #pragma unroll
        for (int k = 0; k < 16; k++)
            g_U[(k * 27 + c) * UCOL + 8 * w2 + jp] = 0.f;
    }
}

// ---------------- Winograd conv kernel: 512 threads, 16 warps x 6 oc ----------------
__global__ __launch_bounds__(512, 1)
void wino_kernel(const float* __restrict__ guide, const float* __restrict__ conv_b) {
    extern __shared__ uint8_t smem[];
    const uint32_t sbase = smem_u32(smem);
    const int tid = threadIdx.x;
    const int wid = tid >> 5;
    const int lane = tid & 31;
    const int bx = blockIdx.x, by = blockIdx.y, bz = blockIdx.z;

    // --- prefetch U_0 into ring slot 0 ---
    {
        const char* src = (const char*)g_U;
        uint32_t dst = sbase + SM_U;
        for (int j = tid; j < UKB / 16; j += 512)
            CP16(dst + j * 16, src + (size_t)j * 16);
        CP_COMMIT();
    }

    if (tid < 96) ((float*)(smem + SM_BIAS))[tid] = (tid < OC) ? conv_b[tid] : 0.f;

    // --- stage input patch: 27 ch x 6 rows x 66 cols (zero-padded), stride 68 ---
    {
        const int py0 = 4 * by - 1;
        const int px0 = 64 * bx - 1;
        float* patch = (float*)(smem + SM_PATCH);
        for (int i = tid; i < 27 * 6 * 66; i += 512) {
            int c = i / 396;
            int rr = (i / 66) % 6;
            int xx = i % 66;
            int gy = py0 + rr;
            int gx = px0 + xx;
            float v = 0.f;
            if ((unsigned)gy < HH && (unsigned)gx < WW)
                v = __ldg(&guide[((size_t)(bz * CHN + c) * HH + gy) * WW + gx]);
            patch[(c * 6 + rr) * 68 + xx] = v;
        }
    }
    __syncthreads();

    // --- input transform V = B^T d B; pair index t = tx + 32*tyl ---
    {
        const float* patch = (const float*)(smem + SM_PATCH);
        float* V = (float*)(smem + SM_V);
        for (int i = tid; i < 27 * 64; i += 512) {
            int c = i >> 6;
            int t = i & 63;
            int tx = t & 31;
            int tyl = t >> 5;
            const float* base = patch + (c * 6 + tyl * 2) * 68 + 2 * tx;
            float d[4][4];
            #pragma unroll
            for (int r = 0; r < 4; r++) {
                float2 p0 = *(const float2*)(base + r * 68);
                float2 p1 = *(const float2*)(base + r * 68 + 2);
                d[r][0] = p0.x; d[r][1] = p0.y; d[r][2] = p1.x; d[r][3] = p1.y;
            }
            float R[4][4];
            #pragma unroll
            for (int r = 0; r < 4; r++) {
                R[r][0] = d[r][0] - d[r][2];
                R[r][1] = d[r][1] + d[r][2];
                R[r][2] = d[r][2] - d[r][1];
                R[r][3] = d[r][1] - d[r][3];
            }
            #pragma unroll
            for (int s = 0; s < 4; s++) {
                V[((0 * 4 + s) * 27 + c) * 64 + t] = R[0][s] - R[2][s];
                V[((1 * 4 + s) * 27 + c) * 64 + t] = R[1][s] + R[2][s];
                V[((2 * 4 + s) * 27 + c) * 64 + t] = R[2][s] - R[1][s];
                V[((3 * 4 + s) * 27 + c) * 64 + t] = R[1][s] - R[3][s];
            }
        }
    }
    __syncthreads();

    // --- 16 position-GEMMs, 3-deep U ring, ONE barrier per iteration ---
    float2 Y[4][6];
    #pragma unroll
    for (int q = 0; q < 4; q++)
        #pragma unroll
        for (int j = 0; j < 6; j++) Y[q][j] = make_float2(0.f, 0.f);

    #pragma unroll 1
    for (int k = 0; k < 16; k++) {
        // prefetch k+1 into slot (k+1)%3; concurrent readers hold slots k%3 and (k-1)%3
        if (k + 1 < 16) {
            const char* src = (const char*)g_U + (size_t)(k + 1) * UKB;
            uint32_t dst = sbase + SM_U + ((k + 1) % 3) * UKB;
            for (int j = tid; j < UKB / 16; j += 512)
                CP16(dst + j * 16, src + j * 16);
            CP_COMMIT();
            CP_WAIT1();
        } else {
            CP_WAIT0();
        }
        __syncthreads();   // cross-thread visibility of U_k

        const float* Uk = (const float*)(smem + SM_U + (k % 3) * UKB) + wid * 8;
        const float2* Vk = (const float2*)(smem + SM_V) + k * 27 * 32 + lane;

        float2 m[6];
        #pragma unroll
        for (int j = 0; j < 6; j++) m[j] = make_float2(0.f, 0.f);
        #pragma unroll 3
        for (int c = 0; c < 27; c++) {
            float2 v = Vk[c * 32];
            float4 ua = *(const float4*)(Uk + c * UCOL);
            float2 ub = *(const float2*)(Uk + c * UCOL + 4);
            m[0].x = fmaf(ua.x, v.x, m[0].x); m[0].y = fmaf(ua.x, v.y, m[0].y);
            m[1].x = fmaf(ua.y, v.x, m[1].x); m[1].y = fmaf(ua.y, v.y, m[1].y);
            m[2].x = fmaf(ua.z, v.x, m[2].x); m[2].y = fmaf(ua.z, v.y, m[2].y);
            m[3].x = fmaf(ua.w, v.x, m[3].x); m[3].y = fmaf(ua.w, v.y, m[3].y);
            m[4].x = fmaf(ub.x, v.x, m[4].x); m[4].y = fmaf(ub.x, v.y, m[4].y);
            m[5].x = fmaf(ub.y, v.x, m[5].x); m[5].y = fmaf(ub.y, v.y, m[5].y);
        }

        // output-transform accumulation: coef(p,q) = A_p[r]*A_q[s]
        int r = k >> 2, s = k & 3;
        float A0r = (r == 3) ? 0.f : 1.f;
        float A1r = (r == 0) ? 0.f : ((r == 1) ? 1.f : -1.f);
        float A0s = (s == 3) ? 0.f : 1.f;
        float A1s = (s == 0) ? 0.f : ((s == 1) ? 1.f : -1.f);
        float cc[4] = { A0r * A0s, A0r * A1s, A1r * A0s, A1r * A1s };
        #pragma unroll
        for (int q = 0; q < 4; q++) {
            if (cc[q] != 0.f) {
                #pragma unroll
                for (int j = 0; j < 6; j++) {
                    Y[q][j].x = fmaf(cc[q], m[j].x, Y[q][j].x);
                    Y[q][j].y = fmaf(cc[q], m[j].y, Y[q][j].y);
                }
            }
        }
        // no end-of-loop barrier: 3-slot ring makes prefetch writes hazard-free
    }

    // --- epilogue: bias + STG.128 ---
    {
        const float* bias = (const float*)(smem + SM_BIAS);
        const int xcol = 64 * bx + 4 * (lane & 15);
        const int row0 = 4 * by + 2 * (lane >> 4);
        const size_t base = (size_t)bz * HWSZ + xcol;
        #pragma unroll
        for (int j = 0; j < 6; j++) {
            int oc = 6 * wid + j;
            if (oc >= OC) break;
            float bv = bias[oc];
            float* plane = g_conv + (size_t)oc * NPIX + base;
            float4 r0v = make_float4(Y[0][j].x + bv, Y[1][j].x + bv,
                                     Y[0][j].y + bv, Y[1][j].y + bv);
            float4 r1v = make_float4(Y[2][j].x + bv, Y[3][j].x + bv,
                                     Y[2][j].y + bv, Y[3][j].y + bv);
            *(float4*)(plane + (size_t)row0 * WW) = r0v;
            *(float4*)(plane + (size_t)(row0 + 1) * WW) = r1v;
        }
    }
}

// ---------------- propagation: softmax + bilinear-zeros + confidence blend ----------------
__device__ __constant__ float TAPX[9] = {-1.f, 0.f, 1.f, -1.f, 0.f, 1.f, -1.f, 0.f, 1.f};
__device__ __constant__ float TAPY[9] = {-1.f, -1.f, -1.f, 0.f, 0.f, 0.f, 1.f, 1.f, 1.f};

__global__ void prop_kernel(const float* __restrict__ prev,
                            const float* __restrict__ sp_dep,
                            const float* __restrict__ confid,
                            float* __restrict__ out_cur,
                            float* __restrict__ pred_out,
                            const float* __restrict__ feat_src,
                            float* __restrict__ feat_dst,
                            int iter) {
    int p = blockIdx.x * blockDim.x + threadIdx.x;
    if (p >= NPIX) return;
    int b = p / HWSZ;
    int rem = p % HWSZ;
    int y = rem / WW;
    int x = rem % WW;
    const float* img = prev + (size_t)b * HWSZ;

    // ---- front-load all independent global reads (max MLP) ----
    float araw[9], ox[9], oy[9];
    #pragma unroll
    for (int t = 0; t < 9; t++)
        araw[t] = __ldg(&g_conv[(size_t)(54 + iter * 9 + t) * NPIX + p]);
    #pragma unroll
    for (int t = 0; t < 9; t++) {
        ox[t] = __ldg(&g_conv[(size_t)((iter * 9 + t) * 2) * NPIX + p]);
        oy[t] = __ldg(&g_conv[(size_t)((iter * 9 + t) * 2 + 1) * NPIX + p]);
    }
    float sp = __ldg(&sp_dep[p]);
    float cfr = __ldg(&confid[p]);

    // softmax weights
    float mx = araw[0];
    #pragma unroll
    for (int t = 1; t < 9; t++) mx = fmaxf(mx, araw[t]);
    float wv[9];
    float s = 0.f;
    #pragma unroll
    for (int t = 0; t < 9; t++) { wv[t] = __expf(araw[t] - mx); s += wv[t]; }
    float inv = 1.f / s;

    float agg = 0.f;
    #pragma unroll
    for (int t = 0; t < 9; t++) {
        float px = ox[t] + TAPX[t] + (float)x;
        float py = oy[t] + TAPY[t] + (float)y;
        float x0f = floorf(px), y0f = floorf(py);
        int xi = (int)x0f, yi = (int)y0f;
        float wx = px - x0f, wy = py - y0f;

        float v00 = 0.f, v01 = 0.f, v10 = 0.f, v11 = 0.f;
        bool xa = (xi >= 0) & (xi < WW);
        bool xb2 = (xi + 1 >= 0) & (xi + 1 < WW);
        bool ya = (yi >= 0) & (yi < HH);
        bool yb = (yi + 1 >= 0) & (yi + 1 < HH);
        if (ya) {
            const float* r0 = img + (size_t)yi * WW;
            if (xa) v00 = __ldg(r0 + xi);
            if (xb2) v01 = __ldg(r0 + xi + 1);
        }
        if (yb) {
            const float* r1 = img + (size_t)(yi + 1) * WW;
            if (xa) v10 = __ldg(r1 + xi);
            if (xb2) v11 = __ldg(r1 + xi + 1);
        }
        float v = (1.f - wy) * ((1.f - wx) * v00 + wx * v01)
                + wy * ((1.f - wx) * v10 + wx * v11);
        agg += wv[t] * v;
    }
    agg *= inv;

    float cf = 1.f / (1.f + __expf(-cfr));
    float sg = (sp > 0.f) ? 1.f : ((sp < 0.f) ? -1.f : 0.f);
    cf *= sg;
    float o = (1.f - cf) * agg + cf * sp;

    out_cur[p] = o;
    if (pred_out) pred_out[p] = o;
    if (feat_dst) feat_dst[p] = feat_src[p];
}

// ---------------- launch ----------------
extern "C" void kernel_launch(void* const* d_in, const int* in_sizes, int n_in,
                              void* d_out, int out_size) {
    const float* input  = (const float*)d_in[0];
    const float* guide  = (const float*)d_in[1];
    const float* sp_dep = (const float*)d_in[2];
    const float* confid = (const float*)d_in[3];
    const float* conv_w = (const float*)d_in[4];
    const float* conv_b = (const float*)d_in[5];

    float* out = (float*)d_out;
    float* pred = out;
    float* feat = out + NPIX;
    float* inter = out + 2 * (size_t)NPIX;

    static bool attr_set = false;
    if (!attr_set) {
        cudaFuncSetAttribute(wino_kernel, cudaFuncAttributeMaxDynamicSharedMemorySize, SM_TOTAL);
        attr_set = true;
    }

    prep_kernel<<<(27 * 96 + 255) / 256, 256>>>(conv_w);

    dim3 wgrid(GX, GY, BB);
    wino_kernel<<<wgrid, 512, SM_TOTAL>>>(guide, conv_b);

    int pb = (NPIX + 255) / 256;
    prop_kernel<<<pb, 256>>>(input, sp_dep, confid, inter, nullptr, input, feat, 0);
    prop_kernel<<<pb, 256>>>(inter, sp_dep, confid, inter + NPIX, nullptr, nullptr, nullptr, 1);
    prop_kernel<<<pb, 256>>>(inter + NPIX, sp_dep, confid, inter + 2 * (size_t)NPIX, pred, nullptr, nullptr, 2);
}